// round 10
// baseline (speedup 1.0000x reference)
#include <cuda_runtime.h>
#include <cuda_fp16.h>

#define N_NODES 40000
#define N_EDGES 640000
#define F 128

// ---------------- scratch (device globals: no allocation allowed) ----------
// g_deg / g_cnt are SELF-RESTORING: zero at module load; scan_kernel re-zeros
// them after consuming, so every kernel_launch call sees zeroed state.
__device__ float    g_deg[N_NODES];
__device__ int      g_cnt[N_NODES];
__device__ float    g_dis[N_NODES];
__device__ int      g_rowptr[N_NODES + 1];
__device__ int      g_cur[N_NODES];
__device__ int2     g_edge[N_EDGES];              // .x = src node, .y = norm (float bits)
__device__ uint2    g_xh [(size_t)N_NODES * 32];  // x in fp16 (4 halfs per uint2)
__device__ uint2    g_y1h[(size_t)N_NODES * 32];  // hop-1 result in fp16
__device__ uint2    g_y2h[(size_t)N_NODES * 32];  // hop-2 result in fp16 (GEMM input)
__device__ int      g_is64;                       // 1 if edge_index stored as int64

// ---------------- fp32 -> fp16 convert + edge width detect -----------------
__global__ void tohalf_kernel(const float4* __restrict__ x4, const int* __restrict__ e32) {
    int i = blockIdx.x * blockDim.x + threadIdx.x;
    if (i == 0) {
        // ids in [0,40000): little-endian int64 => odd 32-bit words all zero.
        int all_zero = 1;
        for (int k = 0; k < 16; k++)
            if (e32[2 * k + 1] != 0) all_zero = 0;
        g_is64 = all_zero;
    }
    if (i < N_NODES * 32) {
        float4 v = x4[i];
        __half2 h0 = __floats2half2_rn(v.x, v.y);
        __half2 h1 = __floats2half2_rn(v.z, v.w);
        uint2 o;
        o.x = *(unsigned*)&h0;
        o.y = *(unsigned*)&h1;
        g_xh[i] = o;
    }
}

__device__ __forceinline__ int edge_src(const int* e32, int e) {
    return g_is64 ? e32[2 * e] : e32[e];
}
__device__ __forceinline__ int edge_dst(const int* e32, int e) {
    return g_is64 ? e32[2 * N_EDGES + 2 * e] : e32[N_EDGES + e];
}

// ---------------- edge-only degree + in-edge histogram ---------------------
// Accumulates onto zeroed g_deg/g_cnt (self-loop handled analytically later).
__global__ void deg_kernel(const int* __restrict__ e32, const float* __restrict__ w) {
    int e = blockIdx.x * blockDim.x + threadIdx.x;
    if (e < N_EDGES) {
        int c = edge_dst(e32, e);
        if ((unsigned)c < N_NODES) {
            atomicAdd(&g_deg[c], w[e]);
            atomicAdd(&g_cnt[c], 1);
        }
    }
}

// ---------------- scan: rowptr/cursors + dis; resets deg/cnt for next call -
__global__ void scan_kernel() {
    __shared__ int sums[1024];
    int t = threadIdx.x;
    const int CH = (N_NODES + 1023) / 1024;   // 40
    int beg = t * CH;
    int end = min(beg + CH, N_NODES);
    int s = 0;
    for (int i = beg; i < end; i++) {
        s += g_cnt[i];
        g_dis[i] = rsqrtf(g_deg[i] + 1.0f);   // +1 = self-loop weight
        g_deg[i] = 0.0f;                       // restore for next call
    }
    sums[t] = s;
    __syncthreads();
    for (int off = 1; off < 1024; off <<= 1) {
        int v = sums[t];
        int add = (t >= off) ? sums[t - off] : 0;
        __syncthreads();
        sums[t] = v + add;
        __syncthreads();
    }
    int run = (t == 0) ? 0 : sums[t - 1];
    for (int i = beg; i < end; i++) {
        g_rowptr[i] = run;
        g_cur[i]    = run;
        run += g_cnt[i];
        g_cnt[i] = 0;                          // restore for next call
    }
    if (t == 0) g_rowptr[N_NODES] = sums[1023];
}

// ---------------- scatter edges into CSR slots, precompute norm ------------
__global__ void scatter_kernel(const int* __restrict__ e32, const float* __restrict__ w) {
    int e = blockIdx.x * blockDim.x + threadIdx.x;
    if (e < N_EDGES) {
        int r = edge_src(e32, e);
        int c = edge_dst(e32, e);
        if ((unsigned)r < N_NODES && (unsigned)c < N_NODES) {
            int p = atomicAdd(&g_cur[c], 1);
            float nm = g_dis[r] * w[e] * g_dis[c];
            g_edge[p] = make_int2(r, __float_as_int(nm));
        }
    }
}

// ---------------- gather helper: 4 fp16 features -> fp32 -------------------
__device__ __forceinline__ void gather_h(const uint2* __restrict__ xh, int node, int lane,
                                         float& f0, float& f1, float& f2, float& f3) {
    uint2 r = __ldg(&xh[(size_t)node * 32 + lane]);
    __half2 a = *(__half2*)&r.x;
    __half2 b = *(__half2*)&r.y;
    float2 fa = __half22float2(a);
    float2 fb = __half22float2(b);
    f0 = fa.x; f1 = fa.y; f2 = fb.x; f3 = fb.y;
}

__device__ __forceinline__ uint2 pack_h(float a, float b, float c, float d) {
    __half2 o0 = __floats2half2_rn(a, b);
    __half2 o1 = __floats2half2_rn(c, d);
    uint2 o;
    o.x = *(unsigned*)&o0;
    o.y = *(unsigned*)&o1;
    return o;
}

// ---------------- one hop: warp per node, fp16 in / fp16 out ---------------
__device__ __forceinline__ void prop_body(const uint2* __restrict__ xin,
                                          uint2* __restrict__ xout) {
    int node = (blockIdx.x * blockDim.x + threadIdx.x) >> 5;
    int lane = threadIdx.x & 31;
    if (node >= N_NODES) return;
    float dis = g_dis[node];
    float sl = dis * dis;                      // self-loop norm
    float v0, v1, v2, v3;
    gather_h(xin, node, lane, v0, v1, v2, v3);
    float ax = sl * v0, ay = sl * v1, az = sl * v2, aw = sl * v3;
    int beg = g_rowptr[node];
    int end = g_rowptr[node + 1];
#pragma unroll 2
    for (int e = beg; e < end; e++) {
        int2 ed = __ldg(&g_edge[e]);           // broadcast across warp
        float nm = __int_as_float(ed.y);
        float x0, x1, x2, x3;
        gather_h(xin, ed.x, lane, x0, x1, x2, x3);
        ax += nm * x0; ay += nm * x1; az += nm * x2; aw += nm * x3;
    }
    xout[(size_t)node * 32 + lane] = pack_h(ax, ay, az, aw);
}

__global__ void __launch_bounds__(256) prop1_kernel() { prop_body(g_xh, g_y1h); }
__global__ void __launch_bounds__(256) prop2_kernel() { prop_body(g_y1h, g_y2h); }

// ---------------- dense linear: out = y2 @ W^T + b (y2 in fp16) ------------
// Block: 256 threads, tile 64 rows x 128 cols. Thread = 8 rows x 4 cols.
#define GM_TM 64
#define GM_KT 16
__global__ void __launch_bounds__(256) gemm_kernel(const float4* __restrict__ Wm4,
                                                   const float* __restrict__ bias,
                                                   float* __restrict__ out) {
    __shared__ float xs[GM_KT][GM_TM + 1];   // [k][row], padded
    __shared__ float ws[GM_KT][F];           // [k][ocol]
    int t  = threadIdx.x;
    int ci = t & 31;     // col group -> cols 4*ci .. 4*ci+3
    int ri = t >> 5;     // row group -> rows 8*ri .. 8*ri+7
    int row0 = blockIdx.x * GM_TM;

    float acc[8][4];
#pragma unroll
    for (int i = 0; i < 8; i++)
#pragma unroll
        for (int j = 0; j < 4; j++) acc[i][j] = 0.0f;

    for (int k0 = 0; k0 < F; k0 += GM_KT) {
        {
            int r  = t >> 2;
            int kq = (t & 3) * 4;
            uint2 hv = g_y2h[(size_t)(row0 + r) * 32 + (k0 + kq) / 4];
            __half2 a = *(__half2*)&hv.x;
            __half2 b = *(__half2*)&hv.y;
            float2 fa = __half22float2(a);
            float2 fb = __half22float2(b);
            xs[kq + 0][r] = fa.x; xs[kq + 1][r] = fa.y;
            xs[kq + 2][r] = fb.x; xs[kq + 3][r] = fb.y;
        }
#pragma unroll
        for (int l = 0; l < 2; l++) {
            int idx = t + l * 256;
            int o   = idx >> 2;
            int kq  = (idx & 3) * 4;
            float4 v = Wm4[((size_t)o * F + k0 + kq) / 4];
            ws[kq + 0][o] = v.x; ws[kq + 1][o] = v.y;
            ws[kq + 2][o] = v.z; ws[kq + 3][o] = v.w;
        }
        __syncthreads();
#pragma unroll
        for (int kk = 0; kk < GM_KT; kk++) {
            float a[8];
#pragma unroll
            for (int j = 0; j < 8; j++) a[j] = xs[kk][ri * 8 + j];       // broadcast
            float b0 = ws[kk][ci * 4 + 0];
            float b1 = ws[kk][ci * 4 + 1];
            float b2 = ws[kk][ci * 4 + 2];
            float b3 = ws[kk][ci * 4 + 3];
#pragma unroll
            for (int i = 0; i < 8; i++) {
                acc[i][0] += a[i] * b0;
                acc[i][1] += a[i] * b1;
                acc[i][2] += a[i] * b2;
                acc[i][3] += a[i] * b3;
            }
        }
        __syncthreads();
    }

#pragma unroll
    for (int i = 0; i < 8; i++) {
        int r = row0 + ri * 8 + i;
        int c = ci * 4;
        float4 v = make_float4(acc[i][0] + bias[c + 0], acc[i][1] + bias[c + 1],
                               acc[i][2] + bias[c + 2], acc[i][3] + bias[c + 3]);
        *(float4*)&out[(size_t)r * F + c] = v;
    }
}

// ---------------------------------------------------------------------------
extern "C" void kernel_launch(void* const* d_in, const int* in_sizes, int n_in,
                              void* d_out, int out_size) {
    const float* x   = (const float*)d_in[0];
    const int*   e32 = (const int*)d_in[1];    // edge_index, width auto-detected
    const float* w   = (const float*)d_in[2];
    const float* Wm  = (const float*)d_in[3];
    const float* b   = (const float*)d_in[4];
    float* out = (float*)d_out;

    const int TB = 256;
    tohalf_kernel<<<(N_NODES * 32 + TB - 1) / TB, TB>>>((const float4*)x, e32);  // 1
    deg_kernel<<<(N_EDGES + TB - 1) / TB, TB>>>(e32, w);                         // 2
    scan_kernel<<<1, 1024>>>();                                                  // 3
    scatter_kernel<<<(N_EDGES + TB - 1) / TB, TB>>>(e32, w);                     // 4

    prop1_kernel<<<N_NODES / 8, 256>>>();                                        // 5
    prop2_kernel<<<N_NODES / 8, 256>>>();                                        // 6
    gemm_kernel<<<N_NODES / GM_TM, 256>>>((const float4*)Wm, b, out);            // 7
}

// round 11
// speedup vs baseline: 1.0237x; 1.0237x over previous
#include <cuda_runtime.h>
#include <cuda_fp16.h>

#define N_NODES 40000
#define N_EDGES 640000
#define F 128

// ---------------- scratch (device globals: no allocation allowed) ----------
// g_deg / g_cnt are SELF-RESTORING: zero at module load; scan_kernel re-zeros
// them after consuming, so every kernel_launch call sees zeroed state.
__device__ float    g_deg[N_NODES];
__device__ int      g_cnt[N_NODES];
__device__ float    g_dis[N_NODES];
__device__ int      g_rowptr[N_NODES + 1];
__device__ int      g_cur[N_NODES];
__device__ int2     g_edge[N_EDGES];              // .x = src node, .y = norm (float bits)
__device__ uint2    g_xh [(size_t)N_NODES * 32];  // x in fp16 (4 halfs per uint2)
__device__ uint2    g_y1h[(size_t)N_NODES * 32];  // hop-1 result in fp16
__device__ uint2    g_y2h[(size_t)N_NODES * 32];  // hop-2 result in fp16 (GEMM A operand)
__device__ unsigned g_wh [F * (F / 2)];           // W in fp16: [o][k], one half2 per entry
__device__ int      g_is64;                       // 1 if edge_index stored as int64

// ---------------- fp32 -> fp16 convert (x and W) + edge width detect -------
__global__ void tohalf_kernel(const float4* __restrict__ x4,
                              const float2* __restrict__ Wm2,
                              const int* __restrict__ e32) {
    int i = blockIdx.x * blockDim.x + threadIdx.x;
    if (i == 0) {
        // ids in [0,40000): little-endian int64 => odd 32-bit words all zero.
        int all_zero = 1;
        for (int k = 0; k < 16; k++)
            if (e32[2 * k + 1] != 0) all_zero = 0;
        g_is64 = all_zero;
    }
    if (i < F * (F / 2)) {                      // convert W: 128 x 64 half2
        float2 v = Wm2[i];
        __half2 h = __floats2half2_rn(v.x, v.y);
        g_wh[i] = *(unsigned*)&h;
    }
    if (i < N_NODES * 32) {
        float4 v = x4[i];
        __half2 h0 = __floats2half2_rn(v.x, v.y);
        __half2 h1 = __floats2half2_rn(v.z, v.w);
        uint2 o;
        o.x = *(unsigned*)&h0;
        o.y = *(unsigned*)&h1;
        g_xh[i] = o;
    }
}

__device__ __forceinline__ int edge_src(const int* e32, int e) {
    return g_is64 ? e32[2 * e] : e32[e];
}
__device__ __forceinline__ int edge_dst(const int* e32, int e) {
    return g_is64 ? e32[2 * N_EDGES + 2 * e] : e32[N_EDGES + e];
}

// ---------------- edge-only degree + in-edge histogram ---------------------
__global__ void deg_kernel(const int* __restrict__ e32, const float* __restrict__ w) {
    int e = blockIdx.x * blockDim.x + threadIdx.x;
    if (e < N_EDGES) {
        int c = edge_dst(e32, e);
        if ((unsigned)c < N_NODES) {
            atomicAdd(&g_deg[c], w[e]);
            atomicAdd(&g_cnt[c], 1);
        }
    }
}

// ---------------- scan: rowptr/cursors + dis; resets deg/cnt for next call -
__global__ void scan_kernel() {
    __shared__ int sums[1024];
    int t = threadIdx.x;
    const int CH = (N_NODES + 1023) / 1024;   // 40
    int beg = t * CH;
    int end = min(beg + CH, N_NODES);
    int s = 0;
    for (int i = beg; i < end; i++) {
        s += g_cnt[i];
        g_dis[i] = rsqrtf(g_deg[i] + 1.0f);   // +1 = self-loop weight
        g_deg[i] = 0.0f;                       // restore for next call
    }
    sums[t] = s;
    __syncthreads();
    for (int off = 1; off < 1024; off <<= 1) {
        int v = sums[t];
        int add = (t >= off) ? sums[t - off] : 0;
        __syncthreads();
        sums[t] = v + add;
        __syncthreads();
    }
    int run = (t == 0) ? 0 : sums[t - 1];
    for (int i = beg; i < end; i++) {
        g_rowptr[i] = run;
        g_cur[i]    = run;
        run += g_cnt[i];
        g_cnt[i] = 0;                          // restore for next call
    }
    if (t == 0) g_rowptr[N_NODES] = sums[1023];
}

// ---------------- scatter edges into CSR slots, precompute norm ------------
__global__ void scatter_kernel(const int* __restrict__ e32, const float* __restrict__ w) {
    int e = blockIdx.x * blockDim.x + threadIdx.x;
    if (e < N_EDGES) {
        int r = edge_src(e32, e);
        int c = edge_dst(e32, e);
        if ((unsigned)r < N_NODES && (unsigned)c < N_NODES) {
            int p = atomicAdd(&g_cur[c], 1);
            float nm = g_dis[r] * w[e] * g_dis[c];
            g_edge[p] = make_int2(r, __float_as_int(nm));
        }
    }
}

// ---------------- gather helper: 4 fp16 features -> fp32 -------------------
__device__ __forceinline__ void gather_h(const uint2* __restrict__ xh, int node, int lane,
                                         float& f0, float& f1, float& f2, float& f3) {
    uint2 r = __ldg(&xh[(size_t)node * 32 + lane]);
    __half2 a = *(__half2*)&r.x;
    __half2 b = *(__half2*)&r.y;
    float2 fa = __half22float2(a);
    float2 fb = __half22float2(b);
    f0 = fa.x; f1 = fa.y; f2 = fb.x; f3 = fb.y;
}

__device__ __forceinline__ uint2 pack_h(float a, float b, float c, float d) {
    __half2 o0 = __floats2half2_rn(a, b);
    __half2 o1 = __floats2half2_rn(c, d);
    uint2 o;
    o.x = *(unsigned*)&o0;
    o.y = *(unsigned*)&o1;
    return o;
}

// ---------------- one hop: warp per node, fp16 in / fp16 out ---------------
__device__ __forceinline__ void prop_body(const uint2* __restrict__ xin,
                                          uint2* __restrict__ xout) {
    int node = (blockIdx.x * blockDim.x + threadIdx.x) >> 5;
    int lane = threadIdx.x & 31;
    if (node >= N_NODES) return;
    float dis = g_dis[node];
    float sl = dis * dis;                      // self-loop norm
    float v0, v1, v2, v3;
    gather_h(xin, node, lane, v0, v1, v2, v3);
    float ax = sl * v0, ay = sl * v1, az = sl * v2, aw = sl * v3;
    int beg = g_rowptr[node];
    int end = g_rowptr[node + 1];
#pragma unroll 2
    for (int e = beg; e < end; e++) {
        int2 ed = __ldg(&g_edge[e]);           // broadcast across warp
        float nm = __int_as_float(ed.y);
        float x0, x1, x2, x3;
        gather_h(xin, ed.x, lane, x0, x1, x2, x3);
        ax += nm * x0; ay += nm * x1; az += nm * x2; aw += nm * x3;
    }
    xout[(size_t)node * 32 + lane] = pack_h(ax, ay, az, aw);
}

__global__ void __launch_bounds__(256) prop1_kernel() { prop_body(g_xh, g_y1h); }
__global__ void __launch_bounds__(256) prop2_kernel() { prop_body(g_y1h, g_y2h); }

// ---------------- tensor-core GEMM: out = y2h @ Wh^T + b -------------------
// Warp computes a 16x128 tile via mma.sync.m16n8k16 (fp16 in, fp32 accum).
// A = g_y2h [40000][128] fp16 row-major; B = g_wh [128][128] fp16 [o][k]
// (row-major over k == col-major operand for mma). Bias pre-loaded into
// accumulators; direct gmem fragment loads per documented lane layout.
__global__ void __launch_bounds__(256) gemm_mma_kernel(const float* __restrict__ bias,
                                                       float* __restrict__ out) {
    int warp = (blockIdx.x * blockDim.x + threadIdx.x) >> 5;
    if (warp >= N_NODES / 16) return;          // 2500 warps exactly
    int lane = threadIdx.x & 31;
    int g  = lane >> 2;                        // group id   (row / n-col)
    int tg = lane & 3;                         // thread-in-group (k / n-pair)
    int row0 = warp * 16;
    const unsigned* A = (const unsigned*)g_y2h;   // [40000][64] u32 (half2)
    const unsigned* B = g_wh;                      // [128][64]   u32 (half2)

    float c[16][4];
#pragma unroll
    for (int n = 0; n < 16; n++) {
        float b0 = bias[n * 8 + tg * 2 + 0];
        float b1 = bias[n * 8 + tg * 2 + 1];
        c[n][0] = b0; c[n][1] = b1; c[n][2] = b0; c[n][3] = b1;
    }

#pragma unroll
    for (int k = 0; k < 8; k++) {              // k0 = 16*k halfs = 8*k u32
        unsigned a0 = A[(size_t)(row0 + g)     * 64 + k * 8 + tg];
        unsigned a1 = A[(size_t)(row0 + g + 8) * 64 + k * 8 + tg];
        unsigned a2 = A[(size_t)(row0 + g)     * 64 + k * 8 + tg + 4];
        unsigned a3 = A[(size_t)(row0 + g + 8) * 64 + k * 8 + tg + 4];
#pragma unroll
        for (int n = 0; n < 16; n++) {
            unsigned b0 = B[(n * 8 + g) * 64 + k * 8 + tg];
            unsigned b1 = B[(n * 8 + g) * 64 + k * 8 + tg + 4];
            asm volatile(
                "mma.sync.aligned.m16n8k16.row.col.f32.f16.f16.f32 "
                "{%0,%1,%2,%3}, {%4,%5,%6,%7}, {%8,%9}, {%0,%1,%2,%3};"
                : "+f"(c[n][0]), "+f"(c[n][1]), "+f"(c[n][2]), "+f"(c[n][3])
                : "r"(a0), "r"(a1), "r"(a2), "r"(a3), "r"(b0), "r"(b1));
        }
    }

#pragma unroll
    for (int n = 0; n < 16; n++) {
        *(float2*)&out[(size_t)(row0 + g)     * F + n * 8 + tg * 2] = make_float2(c[n][0], c[n][1]);
        *(float2*)&out[(size_t)(row0 + g + 8) * F + n * 8 + tg * 2] = make_float2(c[n][2], c[n][3]);
    }
}

// ---------------------------------------------------------------------------
extern "C" void kernel_launch(void* const* d_in, const int* in_sizes, int n_in,
                              void* d_out, int out_size) {
    const float* x   = (const float*)d_in[0];
    const int*   e32 = (const int*)d_in[1];    // edge_index, width auto-detected
    const float* w   = (const float*)d_in[2];
    const float* Wm  = (const float*)d_in[3];
    const float* b   = (const float*)d_in[4];
    float* out = (float*)d_out;

    const int TB = 256;
    tohalf_kernel<<<(N_NODES * 32 + TB - 1) / TB, TB>>>((const float4*)x,
                                                        (const float2*)Wm, e32);  // 1
    deg_kernel<<<(N_EDGES + TB - 1) / TB, TB>>>(e32, w);                          // 2
    scan_kernel<<<1, 1024>>>();                                                   // 3
    scatter_kernel<<<(N_EDGES + TB - 1) / TB, TB>>>(e32, w);                      // 4

    prop1_kernel<<<N_NODES / 8, 256>>>();                                         // 5
    prop2_kernel<<<N_NODES / 8, 256>>>();                                         // 6

    // 2500 warps -> 313 blocks of 8 warps (last block partially active)
    gemm_mma_kernel<<<(N_NODES / 16 + 7) / 8, 256>>>(b, out);                     // 7
}

// round 12
// speedup vs baseline: 1.0304x; 1.0065x over previous
#include <cuda_runtime.h>
#include <cuda_fp16.h>

#define N_NODES 40000
#define N_EDGES 640000
#define F 128

// ---------------- scratch (device globals: no allocation allowed) ----------
// g_deg / g_cnt are SELF-RESTORING: zero at module load; scan_kernel re-zeros
// them after consuming, so every kernel_launch call sees zeroed state.
__device__ float    g_deg[N_NODES];
__device__ int      g_cnt[N_NODES];
__device__ float    g_dis[N_NODES];
__device__ int      g_rowptr[N_NODES + 1];
__device__ int      g_cur[N_NODES];
__device__ int2     g_edge[N_EDGES];              // .x = src node, .y = norm (float bits)
__device__ uint2    g_xh [(size_t)N_NODES * 32];  // x in fp16 (4 halfs per uint2)
__device__ uint2    g_y1h[(size_t)N_NODES * 32];  // hop-1 result in fp16
__device__ uint2    g_y2h[(size_t)N_NODES * 32];  // hop-2 result in fp16 (GEMM A operand)
__device__ unsigned g_wh [F * (F / 2)];           // W in fp16: [o][k], one half2 per entry
__device__ int      g_is64;                       // 1 if edge_index stored as int64

__device__ __forceinline__ int edge_src(const int* e32, int e) {
    return g_is64 ? e32[2 * e] : e32[e];
}
__device__ __forceinline__ int edge_dst(const int* e32, int e) {
    return g_is64 ? e32[2 * N_EDGES + 2 * e] : e32[N_EDGES + e];
}

// ---------------- fused preproc: fp16 convert (x, W) + degree histogram ----
// One grid of N_NODES*32 threads. Thread i: converts x-chunk i; if i<N_EDGES
// also accumulates that edge into deg/cnt. Width-detect done by thread 0
// (deg atomics by other threads in block 0 are ordered after only via the
// separate consumers -> detect must happen before any edge read, so thread 0
// does it first and a grid-wide dependency is enforced by putting edge work
// behind a per-thread read of g_is64 written in THIS kernel -- but atomics
// from other blocks may race ahead of thread 0's write. To stay safe, the
// width detect is computed redundantly per-thread from the first 64 bytes
// (cheap, L1-hot) instead of via a shared flag.
__global__ void pre_kernel(const float4* __restrict__ x4,
                           const float2* __restrict__ Wm2,
                           const int* __restrict__ e32,
                           const float* __restrict__ w) {
    int i = blockIdx.x * blockDim.x + threadIdx.x;

    // per-thread width detect (no cross-thread dependency): ids < 40000 so
    // little-endian int64 storage => odd 32-bit words of the first 16 entries
    // are all zero.
    int is64 = 1;
#pragma unroll
    for (int k = 0; k < 16; k++)
        is64 &= (__ldg(&e32[2 * k + 1]) == 0);
    if (i == 0) g_is64 = is64;   // publish for later kernels

    if (i < F * (F / 2)) {                      // convert W: 128 x 64 half2
        float2 v = Wm2[i];
        __half2 h = __floats2half2_rn(v.x, v.y);
        g_wh[i] = *(unsigned*)&h;
    }
    if (i < N_NODES * 32) {                     // convert x
        float4 v = x4[i];
        __half2 h0 = __floats2half2_rn(v.x, v.y);
        __half2 h1 = __floats2half2_rn(v.z, v.w);
        uint2 o;
        o.x = *(unsigned*)&h0;
        o.y = *(unsigned*)&h1;
        g_xh[i] = o;
    }
    if (i < N_EDGES) {                          // degree histogram
        int c = is64 ? e32[2 * N_EDGES + 2 * i] : e32[N_EDGES + i];
        if ((unsigned)c < N_NODES) {
            atomicAdd(&g_deg[c], w[i]);
            atomicAdd(&g_cnt[c], 1);
        }
    }
}

// ---------------- scan: rowptr/cursors + dis; resets deg/cnt for next call -
__global__ void scan_kernel() {
    __shared__ int sums[1024];
    int t = threadIdx.x;
    const int CH = (N_NODES + 1023) / 1024;   // 40
    int beg = t * CH;
    int end = min(beg + CH, N_NODES);
    int s = 0;
    for (int i = beg; i < end; i++) {
        s += g_cnt[i];
        g_dis[i] = rsqrtf(g_deg[i] + 1.0f);   // +1 = self-loop weight
        g_deg[i] = 0.0f;                       // restore for next call
    }
    sums[t] = s;
    __syncthreads();
    for (int off = 1; off < 1024; off <<= 1) {
        int v = sums[t];
        int add = (t >= off) ? sums[t - off] : 0;
        __syncthreads();
        sums[t] = v + add;
        __syncthreads();
    }
    int run = (t == 0) ? 0 : sums[t - 1];
    for (int i = beg; i < end; i++) {
        g_rowptr[i] = run;
        g_cur[i]    = run;
        run += g_cnt[i];
        g_cnt[i] = 0;                          // restore for next call
    }
    if (t == 0) g_rowptr[N_NODES] = sums[1023];
}

// ---------------- scatter edges into CSR slots, precompute norm ------------
__global__ void scatter_kernel(const int* __restrict__ e32, const float* __restrict__ w) {
    int e = blockIdx.x * blockDim.x + threadIdx.x;
    if (e < N_EDGES) {
        int r = edge_src(e32, e);
        int c = edge_dst(e32, e);
        if ((unsigned)r < N_NODES && (unsigned)c < N_NODES) {
            int p = atomicAdd(&g_cur[c], 1);
            float nm = g_dis[r] * w[e] * g_dis[c];
            g_edge[p] = make_int2(r, __float_as_int(nm));
        }
    }
}

// ---------------- gather helper: 4 fp16 features -> fp32 -------------------
__device__ __forceinline__ void gather_h(const uint2* __restrict__ xh, int node, int lane,
                                         float& f0, float& f1, float& f2, float& f3) {
    uint2 r = __ldg(&xh[(size_t)node * 32 + lane]);
    __half2 a = *(__half2*)&r.x;
    __half2 b = *(__half2*)&r.y;
    float2 fa = __half22float2(a);
    float2 fb = __half22float2(b);
    f0 = fa.x; f1 = fa.y; f2 = fb.x; f3 = fb.y;
}

__device__ __forceinline__ uint2 pack_h(float a, float b, float c, float d) {
    __half2 o0 = __floats2half2_rn(a, b);
    __half2 o1 = __floats2half2_rn(c, d);
    uint2 o;
    o.x = *(unsigned*)&o0;
    o.y = *(unsigned*)&o1;
    return o;
}

// ---------------- one hop: warp per node, fp16 in / fp16 out ---------------
__device__ __forceinline__ void prop_body(const uint2* __restrict__ xin,
                                          uint2* __restrict__ xout) {
    int node = (blockIdx.x * blockDim.x + threadIdx.x) >> 5;
    int lane = threadIdx.x & 31;
    if (node >= N_NODES) return;
    float dis = g_dis[node];
    float sl = dis * dis;                      // self-loop norm
    float v0, v1, v2, v3;
    gather_h(xin, node, lane, v0, v1, v2, v3);
    float ax = sl * v0, ay = sl * v1, az = sl * v2, aw = sl * v3;
    int beg = g_rowptr[node];
    int end = g_rowptr[node + 1];
#pragma unroll 2
    for (int e = beg; e < end; e++) {
        int2 ed = __ldg(&g_edge[e]);           // broadcast across warp
        float nm = __int_as_float(ed.y);
        float x0, x1, x2, x3;
        gather_h(xin, ed.x, lane, x0, x1, x2, x3);
        ax += nm * x0; ay += nm * x1; az += nm * x2; aw += nm * x3;
    }
    xout[(size_t)node * 32 + lane] = pack_h(ax, ay, az, aw);
}

__global__ void __launch_bounds__(256) prop1_kernel() { prop_body(g_xh, g_y1h); }
__global__ void __launch_bounds__(256) prop2_kernel() { prop_body(g_y1h, g_y2h); }

// ---------------- tensor-core GEMM: out = y2h @ Wh^T + b -------------------
// Warp computes a 16x128 tile via mma.sync.m16n8k16 (fp16 in, fp32 accum).
__global__ void __launch_bounds__(256) gemm_mma_kernel(const float* __restrict__ bias,
                                                       float* __restrict__ out) {
    int warp = (blockIdx.x * blockDim.x + threadIdx.x) >> 5;
    if (warp >= N_NODES / 16) return;          // 2500 warps exactly
    int lane = threadIdx.x & 31;
    int g  = lane >> 2;                        // group id   (row / n-col)
    int tg = lane & 3;                         // thread-in-group (k / n-pair)
    int row0 = warp * 16;
    const unsigned* A = (const unsigned*)g_y2h;   // [40000][64] u32 (half2)
    const unsigned* B = g_wh;                      // [128][64]   u32 (half2)

    float c[16][4];
#pragma unroll
    for (int n = 0; n < 16; n++) {
        float b0 = bias[n * 8 + tg * 2 + 0];
        float b1 = bias[n * 8 + tg * 2 + 1];
        c[n][0] = b0; c[n][1] = b1; c[n][2] = b0; c[n][3] = b1;
    }

#pragma unroll
    for (int k = 0; k < 8; k++) {              // k0 = 16*k halfs = 8*k u32
        unsigned a0 = A[(size_t)(row0 + g)     * 64 + k * 8 + tg];
        unsigned a1 = A[(size_t)(row0 + g + 8) * 64 + k * 8 + tg];
        unsigned a2 = A[(size_t)(row0 + g)     * 64 + k * 8 + tg + 4];
        unsigned a3 = A[(size_t)(row0 + g + 8) * 64 + k * 8 + tg + 4];
#pragma unroll
        for (int n = 0; n < 16; n++) {
            unsigned b0 = B[(n * 8 + g) * 64 + k * 8 + tg];
            unsigned b1 = B[(n * 8 + g) * 64 + k * 8 + tg + 4];
            asm volatile(
                "mma.sync.aligned.m16n8k16.row.col.f32.f16.f16.f32 "
                "{%0,%1,%2,%3}, {%4,%5,%6,%7}, {%8,%9}, {%0,%1,%2,%3};"
                : "+f"(c[n][0]), "+f"(c[n][1]), "+f"(c[n][2]), "+f"(c[n][3])
                : "r"(a0), "r"(a1), "r"(a2), "r"(a3), "r"(b0), "r"(b1));
        }
    }

#pragma unroll
    for (int n = 0; n < 16; n++) {
        *(float2*)&out[(size_t)(row0 + g)     * F + n * 8 + tg * 2] = make_float2(c[n][0], c[n][1]);
        *(float2*)&out[(size_t)(row0 + g + 8) * F + n * 8 + tg * 2] = make_float2(c[n][2], c[n][3]);
    }
}

// ---------------------------------------------------------------------------
extern "C" void kernel_launch(void* const* d_in, const int* in_sizes, int n_in,
                              void* d_out, int out_size) {
    const float* x   = (const float*)d_in[0];
    const int*   e32 = (const int*)d_in[1];    // edge_index, width auto-detected
    const float* w   = (const float*)d_in[2];
    const float* Wm  = (const float*)d_in[3];
    const float* b   = (const float*)d_in[4];
    float* out = (float*)d_out;

    const int TB = 256;
    // 6 launches; ncu's capture slot (#4 in recent sessions) lands on prop1.
    pre_kernel<<<(N_NODES * 32 + TB - 1) / TB, TB>>>((const float4*)x,
                                                     (const float2*)Wm, e32, w);  // 1
    scan_kernel<<<1, 1024>>>();                                                   // 2
    scatter_kernel<<<(N_EDGES + TB - 1) / TB, TB>>>(e32, w);                      // 3
    prop1_kernel<<<N_NODES / 8, 256>>>();                                         // 4 <- profiled
    prop2_kernel<<<N_NODES / 8, 256>>>();                                         // 5
    gemm_mma_kernel<<<(N_NODES / 16 + 7) / 8, 256>>>(b, out);                     // 6
}

// round 14
// speedup vs baseline: 1.7349x; 1.6837x over previous
#include <cuda_runtime.h>
#include <cuda_fp16.h>

#define N_NODES 40000
#define N_EDGES 640000
#define F 128
#define GRID 512
#define TPB 256
#define NTHREADS (GRID * TPB)            // 131072
#define NWARPS (NTHREADS / 32)           // 4096
#define CHUNK ((N_NODES + GRID - 1) / GRID)   // 79 (<= TPB)

// ---------------- persistent state (no allocation allowed) -----------------
// g_deg/g_cnt self-restoring (zero at load; reset inside each run).
__device__ float    g_deg[N_NODES];
__device__ int      g_cnt[N_NODES];
__device__ float    g_dis[N_NODES];
__device__ int      g_rowptr[N_NODES + 1];
__device__ int      g_cur[N_NODES];
__device__ int2     g_edge[N_EDGES];               // .x = src*32 (uint2 units), .y = norm bits
__device__ uint2    g_xh [(size_t)N_NODES * 32];   // x fp16 (4 halfs / uint2)
__device__ uint2    g_y1h[(size_t)N_NODES * 32];   // hop-1 fp16
__device__ uint2    g_y2h[(size_t)N_NODES * 32];   // hop-2 fp16 (GEMM A)
__device__ unsigned g_wh [F * (F / 2)];            // W fp16 [o][k] half2
__device__ int      g_bsum[GRID];
__device__ int      g_bscan[GRID];

// grid barrier state: g_arrive returns to 0 after each barrier;
// g_gen increases monotonically (read fresh at each barrier entry).
__device__ unsigned g_arrive;
__device__ volatile unsigned g_gen;

__device__ __forceinline__ void grid_barrier() {
    __syncthreads();
    if (threadIdx.x == 0) {
        __threadfence();                       // publish this block's writes
        unsigned my = g_gen;
        unsigned t = atomicAdd(&g_arrive, 1);
        if (t == GRID - 1) {
            g_arrive = 0;                      // no concurrent arrivals now
            __threadfence();
            g_gen = my + 1;                    // release
        } else {
            while (g_gen == my) { }            // volatile spin (L2)
        }
        __threadfence();
    }
    __syncthreads();
}

// ---------------- fp16 helpers ---------------------------------------------
__device__ __forceinline__ void h2f4(uint2 r, float& f0, float& f1, float& f2, float& f3) {
    __half2 a = *(__half2*)&r.x;
    __half2 b = *(__half2*)&r.y;
    float2 fa = __half22float2(a);
    float2 fb = __half22float2(b);
    f0 = fa.x; f1 = fa.y; f2 = fb.x; f3 = fb.y;
}
__device__ __forceinline__ uint2 pack_h(float a, float b, float c, float d) {
    __half2 o0 = __floats2half2_rn(a, b);
    __half2 o1 = __floats2half2_rn(c, d);
    uint2 o; o.x = *(unsigned*)&o0; o.y = *(unsigned*)&o1; return o;
}

// ---------------- one propagation hop (grid-stride, warp per node) ---------
__device__ __forceinline__ void prop_phase(const uint2* __restrict__ xin,
                                           uint2* __restrict__ xout,
                                           int wg, int lane) {
    for (int node = wg; node < N_NODES; node += NWARPS) {
        float dis = g_dis[node];
        float sl = dis * dis;
        float v0, v1, v2, v3;
        h2f4(__ldg(&xin[(size_t)node * 32 + lane]), v0, v1, v2, v3);
        float ax = sl * v0, ay = sl * v1, az = sl * v2, aw = sl * v3;
        int e   = g_rowptr[node];
        int end = g_rowptr[node + 1];
#pragma unroll 2
        for (; e < end; e++) {
            int2 ed = __ldg(&g_edge[e]);       // broadcast across warp
            float nm = __int_as_float(ed.y);
            float x0, x1, x2, x3;
            h2f4(__ldg(&xin[ed.x + lane]), x0, x1, x2, x3);   // ed.x pre-scaled
            ax += nm * x0; ay += nm * x1; az += nm * x2; aw += nm * x3;
        }
        xout[(size_t)node * 32 + lane] = pack_h(ax, ay, az, aw);
    }
}

// ---------------- the single persistent kernel -----------------------------
__global__ void __launch_bounds__(TPB, 4) sgcn_kernel(
    const float4* __restrict__ x4,
    const float2* __restrict__ Wm2,
    const int*    __restrict__ e32,
    const float*  __restrict__ w,
    const float*  __restrict__ bias,
    float* __restrict__ out)
{
    __shared__ int s_scan[TPB];
    __shared__ int s_is64;

    const int t   = threadIdx.x;
    const int b   = blockIdx.x;
    const int tid = b * TPB + t;
    const int wg   = tid >> 5;
    const int lane = tid & 31;

    // ---- edge width detect (per block; ids<40000 => int64 odd words zero) --
    if (t == 0) {
        int z = 1;
#pragma unroll
        for (int k = 0; k < 16; k++) z &= (__ldg(&e32[2 * k + 1]) == 0);
        s_is64 = z;
    }
    __syncthreads();
    const int is64 = s_is64;

    // ================= P0: convert W, convert x, degree histogram ==========
    if (tid < F * (F / 2)) {
        float2 v = Wm2[tid];
        __half2 h = __floats2half2_rn(v.x, v.y);
        g_wh[tid] = *(unsigned*)&h;
    }
    for (int i = tid; i < N_NODES * 32; i += NTHREADS) {
        float4 v = x4[i];
        g_xh[i] = pack_h(v.x, v.y, v.z, v.w);
    }
    for (int e = tid; e < N_EDGES; e += NTHREADS) {
        int c = is64 ? e32[2 * N_EDGES + 2 * e] : e32[N_EDGES + e];
        if ((unsigned)c < N_NODES) {
            atomicAdd(&g_deg[c], w[e]);
            atomicAdd(&g_cnt[c], 1);
        }
    }
    grid_barrier();                                              // B1

    // ================= P1: dis + block-local scan of cnt ====================
    int nid   = b * CHUNK + t;
    int valid = (t < CHUNK) && (nid < N_NODES);
    int val = 0;
    if (valid) {
        val = g_cnt[nid];
        g_dis[nid] = rsqrtf(g_deg[nid] + 1.0f);    // +1 = self-loop
        g_deg[nid] = 0.0f;                          // restore for next call
    }
    s_scan[t] = val;
    __syncthreads();
#pragma unroll
    for (int off = 1; off < TPB; off <<= 1) {
        int v = s_scan[t];
        int a = (t >= off) ? s_scan[t - off] : 0;
        __syncthreads();
        s_scan[t] = v + a;
        __syncthreads();
    }
    int excl = s_scan[t] - val;                     // exclusive prefix (kept in reg)
    if (t == TPB - 1) g_bsum[b] = s_scan[t];        // block total
    grid_barrier();                                              // B2

    // ================= P2: block 0 scans the 512 block totals ===============
    if (b == 0) {
        int v0 = g_bsum[2 * t], v1 = g_bsum[2 * t + 1];
        int p = v0 + v1;
        s_scan[t] = p;
        __syncthreads();
#pragma unroll
        for (int off = 1; off < TPB; off <<= 1) {
            int v = s_scan[t];
            int a = (t >= off) ? s_scan[t - off] : 0;
            __syncthreads();
            s_scan[t] = v + a;
            __syncthreads();
        }
        int excl2 = s_scan[t] - p;
        g_bscan[2 * t]     = excl2;
        g_bscan[2 * t + 1] = excl2 + v0;
        if (t == TPB - 1) g_rowptr[N_NODES] = s_scan[t];
    }
    grid_barrier();                                              // B3

    // ================= P3: write rowptr / cursors, reset cnt ================
    if (valid) {
        int pos = g_bscan[b] + excl;
        g_rowptr[nid] = pos;
        g_cur[nid]    = pos;
        g_cnt[nid]    = 0;                          // restore for next call
    }
    grid_barrier();                                              // B4

    // ================= P4: scatter edges into CSR ===========================
    for (int e = tid; e < N_EDGES; e += NTHREADS) {
        int r = is64 ? e32[2 * e] : e32[e];
        int c = is64 ? e32[2 * N_EDGES + 2 * e] : e32[N_EDGES + e];
        if ((unsigned)r < N_NODES && (unsigned)c < N_NODES) {
            int p = atomicAdd(&g_cur[c], 1);
            float nm = g_dis[r] * w[e] * g_dis[c];
            g_edge[p] = make_int2(r << 5, __float_as_int(nm));   // pre-scaled src
        }
    }
    grid_barrier();                                              // B5

    // ================= P5/P6: two propagation hops ==========================
    prop_phase(g_xh, g_y1h, wg, lane);
    grid_barrier();                                              // B6
    prop_phase(g_y1h, g_y2h, wg, lane);
    grid_barrier();                                              // B7

    // ================= P7: tensor-core GEMM out = y2h @ Wh^T + b ============
    // Warp tile: 16 rows x 64 cols (mma.m16n8k16, fp16 in, fp32 accum).
    {
        const unsigned* A = (const unsigned*)g_y2h;   // [40000][64] u32
        const unsigned* B = g_wh;                      // [128][64] u32
        int g  = lane >> 2;
        int tg = lane & 3;
        const int NTILES = (N_NODES / 16) * 2;        // 5000
        for (int tile = wg; tile < NTILES; tile += NWARPS) {
            int row0 = (tile >> 1) * 16;
            int h    = (tile & 1) * 64;               // col offset
            float c[8][4];
#pragma unroll
            for (int n = 0; n < 8; n++) {
                float b0 = bias[h + n * 8 + tg * 2 + 0];
                float b1 = bias[h + n * 8 + tg * 2 + 1];
                c[n][0] = b0; c[n][1] = b1; c[n][2] = b0; c[n][3] = b1;
            }
#pragma unroll
            for (int k = 0; k < 8; k++) {
                unsigned a0 = A[(size_t)(row0 + g)     * 64 + k * 8 + tg];
                unsigned a1 = A[(size_t)(row0 + g + 8) * 64 + k * 8 + tg];
                unsigned a2 = A[(size_t)(row0 + g)     * 64 + k * 8 + tg + 4];
                unsigned a3 = A[(size_t)(row0 + g + 8) * 64 + k * 8 + tg + 4];
#pragma unroll
                for (int n = 0; n < 8; n++) {
                    unsigned b0 = B[(h + n * 8 + g) * 64 + k * 8 + tg];
                    unsigned b1 = B[(h + n * 8 + g) * 64 + k * 8 + tg + 4];
                    asm volatile(
                        "mma.sync.aligned.m16n8k16.row.col.f32.f16.f16.f32 "
                        "{%0,%1,%2,%3}, {%4,%5,%6,%7}, {%8,%9}, {%0,%1,%2,%3};"
                        : "+f"(c[n][0]), "+f"(c[n][1]), "+f"(c[n][2]), "+f"(c[n][3])
                        : "r"(a0), "r"(a1), "r"(a2), "r"(a3), "r"(b0), "r"(b1));
                }
            }
#pragma unroll
            for (int n = 0; n < 8; n++) {
                *(float2*)&out[(size_t)(row0 + g)     * F + h + n * 8 + tg * 2] =
                    make_float2(c[n][0], c[n][1]);
                *(float2*)&out[(size_t)(row0 + g + 8) * F + h + n * 8 + tg * 2] =
                    make_float2(c[n][2], c[n][3]);
            }
        }
    }
}

// ---------------------------------------------------------------------------
extern "C" void kernel_launch(void* const* d_in, const int* in_sizes, int n_in,
                              void* d_out, int out_size) {
    const float* x   = (const float*)d_in[0];
    const int*   e32 = (const int*)d_in[1];    // edge_index, width auto-detected
    const float* w   = (const float*)d_in[2];
    const float* Wm  = (const float*)d_in[3];
    const float* b   = (const float*)d_in[4];
    float* out = (float*)d_out;

    sgcn_kernel<<<GRID, TPB>>>((const float4*)x, (const float2*)Wm, e32, w, b, out);
}

// round 16
// speedup vs baseline: 1.7778x; 1.0247x over previous
#include <cuda_runtime.h>
#include <cuda_fp16.h>

#define N_NODES 40000
#define N_EDGES 640000
#define F 128
#define GRID 512
#define TPB 256
#define NTHREADS (GRID * TPB)                 // 131072
#define NWARPS (NTHREADS / 32)                // 4096
#define CHUNK ((N_NODES + GRID - 1) / GRID)   // 79 (<= TPB)

// ---------------- persistent state (no allocation allowed) -----------------
// g_deg/g_cnt/g_ebase self-restoring (zero at load; reset inside each run).
__device__ float    g_deg[N_NODES];
__device__ int      g_cnt[N_NODES];
__device__ float    g_dis[N_NODES];
__device__ int      g_rowptr[N_NODES];
__device__ int      g_cur[N_NODES];            // after scatter: end of node's range
__device__ int2     g_edge[N_EDGES];           // .x = src*32 (uint2 units), .y = norm bits
__device__ uint2    g_xh [(size_t)N_NODES * 32];
__device__ uint2    g_y1h[(size_t)N_NODES * 32];
__device__ uint2    g_y2h[(size_t)N_NODES * 32];
__device__ unsigned g_wh [F * (F / 2)];        // W fp16 [o][k] half2
__device__ int      g_ebase;                   // running CSR base (reset each run)

// grid barrier: g_arrive returns to 0 after each barrier; g_gen monotonic.
__device__ unsigned g_arrive;
__device__ volatile unsigned g_gen;

__device__ __forceinline__ void grid_barrier() {
    __syncthreads();
    if (threadIdx.x == 0) {
        __threadfence();
        unsigned my = g_gen;
        unsigned t = atomicAdd(&g_arrive, 1);
        if (t == GRID - 1) {
            g_arrive = 0;
            __threadfence();
            g_gen = my + 1;
        } else {
            while (g_gen == my) { }
        }
        __threadfence();
    }
    __syncthreads();
}

// ---------------- fp16 helpers ---------------------------------------------
__device__ __forceinline__ void h2f4(uint2 r, float& f0, float& f1, float& f2, float& f3) {
    __half2 a = *(__half2*)&r.x;
    __half2 b = *(__half2*)&r.y;
    float2 fa = __half22float2(a);
    float2 fb = __half22float2(b);
    f0 = fa.x; f1 = fa.y; f2 = fb.x; f3 = fb.y;
}
__device__ __forceinline__ uint2 pack_h(float a, float b, float c, float d) {
    __half2 o0 = __floats2half2_rn(a, b);
    __half2 o1 = __floats2half2_rn(c, d);
    uint2 o; o.x = *(unsigned*)&o0; o.y = *(unsigned*)&o1; return o;
}

// ---------------- one propagation hop (grid-stride, warp per node) ---------
__device__ __forceinline__ void prop_phase(const uint2* __restrict__ xin,
                                           uint2* __restrict__ xout,
                                           int wg, int lane) {
    for (int node = wg; node < N_NODES; node += NWARPS) {
        float dis = g_dis[node];
        float sl = dis * dis;
        float v0, v1, v2, v3;
        h2f4(__ldg(&xin[(size_t)node * 32 + lane]), v0, v1, v2, v3);
        float ax = sl * v0, ay = sl * v1, az = sl * v2, aw = sl * v3;
        int e   = g_rowptr[node];
        int end = g_cur[node];                 // == rowptr + cnt after scatter
#pragma unroll 2
        for (; e < end; e++) {
            int2 ed = __ldg(&g_edge[e]);       // broadcast across warp
            float nm = __int_as_float(ed.y);
            float x0, x1, x2, x3;
            h2f4(__ldg(&xin[ed.x + lane]), x0, x1, x2, x3);   // ed.x pre-scaled
            ax += nm * x0; ay += nm * x1; az += nm * x2; aw += nm * x3;
        }
        xout[(size_t)node * 32 + lane] = pack_h(ax, ay, az, aw);
    }
}

// ---------------- the single persistent kernel -----------------------------
__global__ void __launch_bounds__(TPB, 6) sgcn_kernel(
    const float4* __restrict__ x4,
    const float2* __restrict__ Wm2,
    const int*    __restrict__ e32,
    const float*  __restrict__ w,
    const float*  __restrict__ bias,
    float* __restrict__ out)
{
    __shared__ int s_scan[TPB];
    __shared__ int s_base;
    __shared__ int s_is64;

    const int t   = threadIdx.x;
    const int b   = blockIdx.x;
    const int tid = b * TPB + t;
    const int wg   = tid >> 5;
    const int lane = tid & 31;

    // ---- per-block edge width detect (ids<40000 => int64 odd words zero) ---
    if (t == 0) {
        int z = 1;
#pragma unroll
        for (int k = 0; k < 16; k++) z &= (__ldg(&e32[2 * k + 1]) == 0);
        s_is64 = z;
    }
    __syncthreads();
    const int is64 = s_is64;

    // ================= P0: degree histogram =================================
    for (int e = tid; e < N_EDGES; e += NTHREADS) {
        int c = is64 ? e32[2 * N_EDGES + 2 * e] : e32[N_EDGES + e];
        if ((unsigned)c < N_NODES) {
            atomicAdd(&g_deg[c], w[e]);
            atomicAdd(&g_cnt[c], 1);
        }
    }
    grid_barrier();                                              // B1

    // ================= P1: dis + block scan + atomic base -> rowptr/cur =====
    {
        int nid   = b * CHUNK + t;
        int valid = (t < CHUNK) && (nid < N_NODES);
        int val = 0;
        if (valid) {
            val = g_cnt[nid];
            g_dis[nid] = rsqrtf(g_deg[nid] + 1.0f);   // +1 = self-loop
            g_deg[nid] = 0.0f;                         // restore for next call
            g_cnt[nid] = 0;                            // restore for next call
        }
        s_scan[t] = val;
        __syncthreads();
#pragma unroll
        for (int off = 1; off < TPB; off <<= 1) {
            int v = s_scan[t];
            int a = (t >= off) ? s_scan[t - off] : 0;
            __syncthreads();
            s_scan[t] = v + a;
            __syncthreads();
        }
        int excl = s_scan[t] - val;
        if (t == TPB - 1) s_base = atomicAdd(&g_ebase, s_scan[t]);
        __syncthreads();
        if (valid) {
            int pos = s_base + excl;
            g_rowptr[nid] = pos;
            g_cur[nid]    = pos;
        }
    }
    grid_barrier();                                              // B2

    // ================= P2: scatter edges + convert x + convert W ============
    if (tid == 0) g_ebase = 0;                    // restore for next call
    if (tid < F * (F / 2)) {
        float2 v = Wm2[tid];
        __half2 h = __floats2half2_rn(v.x, v.y);
        g_wh[tid] = *(unsigned*)&h;
    }
    for (int i = tid; i < N_NODES * 32; i += NTHREADS) {
        float4 v = x4[i];
        g_xh[i] = pack_h(v.x, v.y, v.z, v.w);
    }
    for (int e = tid; e < N_EDGES; e += NTHREADS) {
        int r = is64 ? e32[2 * e] : e32[e];
        int c = is64 ? e32[2 * N_EDGES + 2 * e] : e32[N_EDGES + e];
        if ((unsigned)r < N_NODES && (unsigned)c < N_NODES) {
            int p = atomicAdd(&g_cur[c], 1);
            float nm = g_dis[r] * w[e] * g_dis[c];
            g_edge[p] = make_int2(r << 5, __float_as_int(nm));   // pre-scaled src
        }
    }
    grid_barrier();                                              // B3

    // ================= P3/P4: two propagation hops ==========================
    prop_phase(g_xh, g_y1h, wg, lane);
    grid_barrier();                                              // B4
    prop_phase(g_y1h, g_y2h, wg, lane);
    grid_barrier();                                              // B5

    // ================= P5: tensor-core GEMM out = y2h @ Wh^T + b ============
    // Warp tile: 16 rows x 32 cols (mma.m16n8k16, fp16 in, fp32 accum).
    {
        const unsigned* A = (const unsigned*)g_y2h;   // [40000][64] u32
        const unsigned* B = g_wh;                      // [128][64] u32
        int g  = lane >> 2;
        int tg = lane & 3;
        const int NTILES = (N_NODES / 16) * 4;        // 10000
        for (int tile = wg; tile < NTILES; tile += NWARPS) {
            int row0 = (tile >> 2) * 16;
            int h    = (tile & 3) * 32;               // col offset
            float c[4][4];
#pragma unroll
            for (int n = 0; n < 4; n++) {
                float b0 = bias[h + n * 8 + tg * 2 + 0];
                float b1 = bias[h + n * 8 + tg * 2 + 1];
                c[n][0] = b0; c[n][1] = b1; c[n][2] = b0; c[n][3] = b1;
            }
#pragma unroll
            for (int k = 0; k < 8; k++) {
                unsigned a0 = A[(size_t)(row0 + g)     * 64 + k * 8 + tg];
                unsigned a1 = A[(size_t)(row0 + g + 8) * 64 + k * 8 + tg];
                unsigned a2 = A[(size_t)(row0 + g)     * 64 + k * 8 + tg + 4];
                unsigned a3 = A[(size_t)(row0 + g + 8) * 64 + k * 8 + tg + 4];
#pragma unroll
                for (int n = 0; n < 4; n++) {
                    unsigned b0 = B[(h + n * 8 + g) * 64 + k * 8 + tg];
                    unsigned b1 = B[(h + n * 8 + g) * 64 + k * 8 + tg + 4];
                    asm volatile(
                        "mma.sync.aligned.m16n8k16.row.col.f32.f16.f16.f32 "
                        "{%0,%1,%2,%3}, {%4,%5,%6,%7}, {%8,%9}, {%0,%1,%2,%3};"
                        : "+f"(c[n][0]), "+f"(c[n][1]), "+f"(c[n][2]), "+f"(c[n][3])
                        : "r"(a0), "r"(a1), "r"(a2), "r"(a3), "r"(b0), "r"(b1));
                }
            }
#pragma unroll
            for (int n = 0; n < 4; n++) {
                *(float2*)&out[(size_t)(row0 + g)     * F + h + n * 8 + tg * 2] =
                    make_float2(c[n][0], c[n][1]);
                *(float2*)&out[(size_t)(row0 + g + 8) * F + h + n * 8 + tg * 2] =
                    make_float2(c[n][2], c[n][3]);
            }
        }
    }
}

// ---------------------------------------------------------------------------
extern "C" void kernel_launch(void* const* d_in, const int* in_sizes, int n_in,
                              void* d_out, int out_size) {
    const float* x   = (const float*)d_in[0];
    const int*   e32 = (const int*)d_in[1];    // edge_index, width auto-detected
    const float* w   = (const float*)d_in[2];
    const float* Wm  = (const float*)d_in[3];
    const float* b   = (const float*)d_in[4];
    float* out = (float*)d_out;

    sgcn_kernel<<<GRID, TPB>>>((const float4*)x, (const float2*)Wm, e32, w, b, out);
}

// round 17
// speedup vs baseline: 2.0687x; 1.1636x over previous
#include <cuda_runtime.h>
#include <cuda_fp16.h>

#define N_NODES 40000
#define N_EDGES 640000
#define F 128
#define GRID 888                              // 6 blocks/SM x 148 SMs, all co-resident
#define TPB 256
#define NTHREADS (GRID * TPB)                 // 227328
#define NWARPS (NTHREADS / 32)                // 7104
#define CHUNK ((N_NODES + GRID - 1) / GRID)   // 46 (<= TPB)

// ---------------- persistent state (no allocation allowed) -----------------
// g_deg/g_cnt/g_ebase self-restoring (zero at load; reset inside each run).
__device__ float    g_deg[N_NODES];
__device__ int      g_cnt[N_NODES];
__device__ float    g_dis[N_NODES];
__device__ int      g_rowptr[N_NODES];
__device__ int      g_cur[N_NODES];            // after scatter: end of node's range
__device__ int2     g_edge[N_EDGES];           // .x = src*32 (uint2 units), .y = norm bits
__device__ uint2    g_xh [(size_t)N_NODES * 32];
__device__ uint2    g_y1h[(size_t)N_NODES * 32];
__device__ uint2    g_y2h[(size_t)N_NODES * 32];
__device__ unsigned g_wh [F * (F / 2)];        // W fp16 [o][k] half2
__device__ int      g_ebase;                   // running CSR base (reset each run)

// grid barrier: g_arrive returns to 0 after each barrier; g_gen monotonic.
__device__ unsigned g_arrive;
__device__ volatile unsigned g_gen;

__device__ __forceinline__ void grid_barrier() {
    __syncthreads();
    if (threadIdx.x == 0) {
        __threadfence();
        unsigned my = g_gen;
        unsigned t = atomicAdd(&g_arrive, 1);
        if (t == GRID - 1) {
            g_arrive = 0;
            __threadfence();
            g_gen = my + 1;
        } else {
            while (g_gen == my) { }
        }
        __threadfence();
    }
    __syncthreads();
}

// ---------------- fp16 helpers ---------------------------------------------
__device__ __forceinline__ void h2f4(uint2 r, float& f0, float& f1, float& f2, float& f3) {
    __half2 a = *(__half2*)&r.x;
    __half2 b = *(__half2*)&r.y;
    float2 fa = __half22float2(a);
    float2 fb = __half22float2(b);
    f0 = fa.x; f1 = fa.y; f2 = fb.x; f3 = fb.y;
}
__device__ __forceinline__ uint2 pack_h(float a, float b, float c, float d) {
    __half2 o0 = __floats2half2_rn(a, b);
    __half2 o1 = __floats2half2_rn(c, d);
    uint2 o; o.x = *(unsigned*)&o0; o.y = *(unsigned*)&o1; return o;
}

// ---------------- one propagation hop (grid-stride, warp per node) ---------
__device__ __forceinline__ void prop_phase(const uint2* __restrict__ xin,
                                           uint2* __restrict__ xout,
                                           int wg, int lane) {
    for (int node = wg; node < N_NODES; node += NWARPS) {
        float dis = g_dis[node];
        float sl = dis * dis;
        float v0, v1, v2, v3;
        h2f4(__ldg(&xin[(size_t)node * 32 + lane]), v0, v1, v2, v3);
        float ax = sl * v0, ay = sl * v1, az = sl * v2, aw = sl * v3;
        int e   = g_rowptr[node];
        int end = g_cur[node];                 // == rowptr + cnt after scatter
#pragma unroll 2
        for (; e < end; e++) {
            int2 ed = __ldg(&g_edge[e]);       // broadcast across warp
            float nm = __int_as_float(ed.y);
            float x0, x1, x2, x3;
            h2f4(__ldg(&xin[ed.x + lane]), x0, x1, x2, x3);   // ed.x pre-scaled
            ax += nm * x0; ay += nm * x1; az += nm * x2; aw += nm * x3;
        }
        xout[(size_t)node * 32 + lane] = pack_h(ax, ay, az, aw);
    }
}

// ---------------- the single persistent kernel -----------------------------
__global__ void __launch_bounds__(TPB, 6) sgcn_kernel(
    const float4* __restrict__ x4,
    const float2* __restrict__ Wm2,
    const int*    __restrict__ e32,
    const float*  __restrict__ w,
    const float*  __restrict__ bias,
    float* __restrict__ out)
{
    __shared__ int s_scan[TPB];
    __shared__ int s_base;
    __shared__ int s_is64;

    const int t   = threadIdx.x;
    const int b   = blockIdx.x;
    const int tid = b * TPB + t;
    const int wg   = tid >> 5;
    const int lane = tid & 31;

    // ---- per-block edge width detect (ids<40000 => int64 odd words zero) ---
    if (t == 0) {
        int z = 1;
#pragma unroll
        for (int k = 0; k < 16; k++) z &= (__ldg(&e32[2 * k + 1]) == 0);
        s_is64 = z;
    }
    __syncthreads();
    const int is64 = s_is64;

    // ================= P0: degree histogram =================================
    for (int e = tid; e < N_EDGES; e += NTHREADS) {
        int c = is64 ? e32[2 * N_EDGES + 2 * e] : e32[N_EDGES + e];
        if ((unsigned)c < N_NODES) {
            atomicAdd(&g_deg[c], w[e]);
            atomicAdd(&g_cnt[c], 1);
        }
    }
    grid_barrier();                                              // B1

    // ================= P1: dis + block scan + atomic base -> rowptr/cur =====
    {
        int nid   = b * CHUNK + t;
        int valid = (t < CHUNK) && (nid < N_NODES);
        int val = 0;
        if (valid) {
            val = g_cnt[nid];
            g_dis[nid] = rsqrtf(g_deg[nid] + 1.0f);   // +1 = self-loop
            g_deg[nid] = 0.0f;                         // restore for next call
            g_cnt[nid] = 0;                            // restore for next call
        }
        s_scan[t] = val;
        __syncthreads();
#pragma unroll
        for (int off = 1; off < TPB; off <<= 1) {
            int v = s_scan[t];
            int a = (t >= off) ? s_scan[t - off] : 0;
            __syncthreads();
            s_scan[t] = v + a;
            __syncthreads();
        }
        int excl = s_scan[t] - val;
        if (t == TPB - 1) s_base = atomicAdd(&g_ebase, s_scan[t]);
        __syncthreads();
        if (valid) {
            int pos = s_base + excl;
            g_rowptr[nid] = pos;
            g_cur[nid]    = pos;
        }
    }
    grid_barrier();                                              // B2

    // ================= P2: scatter edges + convert x + convert W ============
    if (tid == 0) g_ebase = 0;                    // restore for next call
    if (tid < F * (F / 2)) {
        float2 v = Wm2[tid];
        __half2 h = __floats2half2_rn(v.x, v.y);
        g_wh[tid] = *(unsigned*)&h;
    }
    for (int i = tid; i < N_NODES * 32; i += NTHREADS) {
        float4 v = x4[i];
        g_xh[i] = pack_h(v.x, v.y, v.z, v.w);
    }
    for (int e = tid; e < N_EDGES; e += NTHREADS) {
        int r = is64 ? e32[2 * e] : e32[e];
        int c = is64 ? e32[2 * N_EDGES + 2 * e] : e32[N_EDGES + e];
        if ((unsigned)r < N_NODES && (unsigned)c < N_NODES) {
            int p = atomicAdd(&g_cur[c], 1);
            float nm = g_dis[r] * w[e] * g_dis[c];
            g_edge[p] = make_int2(r << 5, __float_as_int(nm));   // pre-scaled src
        }
    }
    grid_barrier();                                              // B3

    // ================= P3/P4: two propagation hops ==========================
    prop_phase(g_xh, g_y1h, wg, lane);
    grid_barrier();                                              // B4
    prop_phase(g_y1h, g_y2h, wg, lane);
    grid_barrier();                                              // B5

    // ================= P5: tensor-core GEMM out = y2h @ Wh^T + b ============
    // Warp tile: 16 rows x 32 cols (mma.m16n8k16, fp16 in, fp32 accum).
    {
        const unsigned* A = (const unsigned*)g_y2h;   // [40000][64] u32
        const unsigned* B = g_wh;                      // [128][64] u32
        int g  = lane >> 2;
        int tg = lane & 3;
        const int NTILES = (N_NODES / 16) * 4;        // 10000
        for (int tile = wg; tile < NTILES; tile += NWARPS) {
            int row0 = (tile >> 2) * 16;
            int h    = (tile & 3) * 32;               // col offset
            float c[4][4];
#pragma unroll
            for (int n = 0; n < 4; n++) {
                float b0 = bias[h + n * 8 + tg * 2 + 0];
                float b1 = bias[h + n * 8 + tg * 2 + 1];
                c[n][0] = b0; c[n][1] = b1; c[n][2] = b0; c[n][3] = b1;
            }
#pragma unroll
            for (int k = 0; k < 8; k++) {
                unsigned a0 = A[(size_t)(row0 + g)     * 64 + k * 8 + tg];
                unsigned a1 = A[(size_t)(row0 + g + 8) * 64 + k * 8 + tg];
                unsigned a2 = A[(size_t)(row0 + g)     * 64 + k * 8 + tg + 4];
                unsigned a3 = A[(size_t)(row0 + g + 8) * 64 + k * 8 + tg + 4];
#pragma unroll
                for (int n = 0; n < 4; n++) {
                    unsigned b0 = B[(h + n * 8 + g) * 64 + k * 8 + tg];
                    unsigned b1 = B[(h + n * 8 + g) * 64 + k * 8 + tg + 4];
                    asm volatile(
                        "mma.sync.aligned.m16n8k16.row.col.f32.f16.f16.f32 "
                        "{%0,%1,%2,%3}, {%4,%5,%6,%7}, {%8,%9}, {%0,%1,%2,%3};"
                        : "+f"(c[n][0]), "+f"(c[n][1]), "+f"(c[n][2]), "+f"(c[n][3])
                        : "r"(a0), "r"(a1), "r"(a2), "r"(a3), "r"(b0), "r"(b1));
                }
            }
#pragma unroll
            for (int n = 0; n < 4; n++) {
                *(float2*)&out[(size_t)(row0 + g)     * F + h + n * 8 + tg * 2] =
                    make_float2(c[n][0], c[n][1]);
                *(float2*)&out[(size_t)(row0 + g + 8) * F + h + n * 8 + tg * 2] =
                    make_float2(c[n][2], c[n][3]);
            }
        }
    }
}

// ---------------------------------------------------------------------------
extern "C" void kernel_launch(void* const* d_in, const int* in_sizes, int n_in,
                              void* d_out, int out_size) {
    const float* x   = (const float*)d_in[0];
    const int*   e32 = (const int*)d_in[1];    // edge_index, width auto-detected
    const float* w   = (const float*)d_in[2];
    const float* Wm  = (const float*)d_in[3];
    const float* b   = (const float*)d_in[4];
    float* out = (float*)d_out;

    sgcn_kernel<<<GRID, TPB>>>((const float4*)x, (const float2*)Wm, e32, w, b, out);
}